// round 11
// baseline (speedup 1.0000x reference)
#include <cuda_runtime.h>
#include <mma.h>
using namespace nvcuda;

#define NN 50000
#define NNP 50048          // padded to multiple of 128 for full-tile tensor stores
#define NE 800000
#define D_IN 256
#define D_HID 128
#define D_OUT 64

#define SCAN_B 1024
#define SCAN_NBLK ((NN + SCAN_B - 1) / SCAN_B)   // 49

// ---------------- static device scratch ----------------
__device__ float g_bufA[(size_t)NNP * D_HID];
__device__ float g_bufB[(size_t)NNP * D_HID];
__device__ float g_dinv[NN];
__device__ int   g_deg[NN];
__device__ int   g_rowptr[NN + 1];
__device__ int   g_fill[NN];
__device__ int   g_blocksums[SCAN_NBLK];
__device__ int   g_csr_src[NE];
__device__ float g_csr_w[NE];
__device__ int   g_is64;

// ---------------- edge index accessors ----------------
__device__ __forceinline__ int edge_src(const int* ei, int e) {
    if (g_is64) return ei[2 * e];
    return ei[e];
}
__device__ __forceinline__ int edge_dst(const int* ei, int e) {
    if (g_is64) return ei[2 * NE + 2 * e];
    return ei[NE + e];
}

// ---------------- prep: zero degrees + dtype detect fused ----------------
__global__ void k_zero_detect(const int* __restrict__ ei) {
    int i = blockIdx.x * blockDim.x + threadIdx.x;
    if (i < NN) g_deg[i] = 0;
    if (i == 0) {
        int allzero = 1;
        for (int k = 0; k < 64; k++) {
            int idx = 2 * (k * (NE / 64) + 1) + 1;
            if (ei[idx] != 0) { allzero = 0; break; }
        }
        g_is64 = allzero;
    }
}

__global__ void k_degcount(const int* __restrict__ ei) {
    int e = blockIdx.x * blockDim.x + threadIdx.x;
    if (e >= NE) return;
    int d = edge_dst(ei, e);
    if ((unsigned)d < NN) atomicAdd(&g_deg[d], 1);
}

__global__ void __launch_bounds__(SCAN_B) k_scan1() {
    __shared__ int sh[SCAN_B];
    int i = blockIdx.x * SCAN_B + threadIdx.x;
    int v = (i < NN) ? g_deg[i] : 0;
    sh[threadIdx.x] = v;
    __syncthreads();
    for (int off = 1; off < SCAN_B; off <<= 1) {
        int t = (threadIdx.x >= (unsigned)off) ? sh[threadIdx.x - off] : 0;
        __syncthreads();
        sh[threadIdx.x] += t;
        __syncthreads();
    }
    if (i < NN) g_rowptr[i] = sh[threadIdx.x] - v;
    if (threadIdx.x == SCAN_B - 1) g_blocksums[blockIdx.x] = sh[SCAN_B - 1];
}

// finalize scan (block-local redundant scan of 49 block sums) + fill reset + dinv
__global__ void k_scan_fin() {
    __shared__ int pref[SCAN_NBLK];
    if (threadIdx.x == 0) {
        int acc = 0;
        for (int b = 0; b < SCAN_NBLK; b++) {
            pref[b] = acc;
            acc += g_blocksums[b];
        }
    }
    __syncthreads();
    int i = blockIdx.x * blockDim.x + threadIdx.x;
    if (i < NN) {
        g_rowptr[i] += pref[i / SCAN_B];
        g_fill[i] = 0;
        g_dinv[i] = rsqrtf((float)(g_deg[i] + 1));  // +1 self loop
    }
    if (i == 0) g_rowptr[NN] = NE;
}

__global__ void k_fill(const int* __restrict__ ei) {
    int e = blockIdx.x * blockDim.x + threadIdx.x;
    if (e >= NE) return;
    int s = edge_src(ei, e);
    int d = edge_dst(ei, e);
    if ((unsigned)s >= NN || (unsigned)d >= NN) return;
    int pos = g_rowptr[d] + atomicAdd(&g_fill[d], 1);
    g_csr_src[pos] = s;
    g_csr_w[pos] = g_dinv[s] * g_dinv[d];
}

// ---------------- tensor-core GEMM (tf32 wmma), tf32 conversion at staging ----------------
template <int BN>
__global__ void __launch_bounds__(256) k_gemm_tc(const float* __restrict__ Xext, int xsel, int osel,
                                                 const float* __restrict__ W, int M, int K) {
    constexpr int BM = 128;
    constexpr int BK = 32;
    constexpr int XPAD = 4;
    constexpr int WPAD = 8;
    constexpr int CF = BN / 32;

    const float* X = (xsel < 0) ? Xext : (xsel == 0 ? g_bufA : g_bufB);
    float* H = (osel == 0) ? g_bufA : g_bufB;

    __shared__ float Xs[BM][BK + XPAD];
    __shared__ float Ws[BK][BN + WPAD];

    const int t = threadIdx.x;
    const int warp = t >> 5;
    const int wr = warp & 3;
    const int wc = warp >> 2;
    const int m0 = blockIdx.x * BM;

    wmma::fragment<wmma::accumulator, 16, 16, 8, float> c[2][CF];
#pragma unroll
    for (int i = 0; i < 2; i++)
#pragma unroll
        for (int j = 0; j < CF; j++) wmma::fill_fragment(c[i][j], 0.0f);

    for (int kb = 0; kb < K; kb += BK) {
#pragma unroll
        for (int it = 0; it < (BM * BK / 4) / 256; it++) {
            int idx = t + it * 256;
            int r = idx >> 3;
            int kq = idx & 7;
            float4 v = make_float4(0.f, 0.f, 0.f, 0.f);
            int gr = m0 + r;
            if (gr < M) v = *(const float4*)&X[(size_t)gr * K + kb + kq * 4];
            v.x = wmma::__float_to_tf32(v.x);
            v.y = wmma::__float_to_tf32(v.y);
            v.z = wmma::__float_to_tf32(v.z);
            v.w = wmma::__float_to_tf32(v.w);
            *(float4*)&Xs[r][kq * 4] = v;
        }
#pragma unroll
        for (int it = 0; it < (BK * BN / 4) / 256; it++) {
            int idx = t + it * 256;
            int r = idx / (BN / 4);
            int c4 = idx % (BN / 4);
            float4 v = *(const float4*)&W[(size_t)(kb + r) * BN + c4 * 4];
            v.x = wmma::__float_to_tf32(v.x);
            v.y = wmma::__float_to_tf32(v.y);
            v.z = wmma::__float_to_tf32(v.z);
            v.w = wmma::__float_to_tf32(v.w);
            *(float4*)&Ws[r][c4 * 4] = v;
        }
        __syncthreads();

#pragma unroll
        for (int ks = 0; ks < BK / 8; ks++) {
            wmma::fragment<wmma::matrix_a, 16, 16, 8, wmma::precision::tf32, wmma::row_major> a[2];
            wmma::fragment<wmma::matrix_b, 16, 16, 8, wmma::precision::tf32, wmma::row_major> b[CF];
#pragma unroll
            for (int i = 0; i < 2; i++)
                wmma::load_matrix_sync(a[i], &Xs[wr * 32 + i * 16][ks * 8], BK + XPAD);
#pragma unroll
            for (int j = 0; j < CF; j++)
                wmma::load_matrix_sync(b[j], &Ws[ks * 8][wc * (BN / 2) + j * 16], BN + WPAD);
#pragma unroll
            for (int i = 0; i < 2; i++)
#pragma unroll
                for (int j = 0; j < CF; j++)
                    wmma::mma_sync(c[i][j], a[i], b[j], c[i][j]);
        }
        __syncthreads();
    }

#pragma unroll
    for (int i = 0; i < 2; i++) {
        int gr0 = m0 + wr * 32 + i * 16;
#pragma unroll
        for (int j = 0; j < CF; j++) {
            int gc0 = wc * (BN / 2) + j * 16;
            wmma::store_matrix_sync(&H[(size_t)gr0 * BN + gc0], c[i][j], BN, wmma::mem_row_major);
        }
    }
}

// ---------------- fused gather F=128: warp/node, edge loop unrolled x4 ----------------
__global__ void __launch_bounds__(256) k_gather128(int hsel, int osel,
                                                   const float* __restrict__ bias) {
    const float* __restrict__ h = (hsel == 0) ? g_bufA : g_bufB;
    float* __restrict__ out = (osel == 0) ? g_bufA : g_bufB;

    int warp = (blockIdx.x * blockDim.x + threadIdx.x) >> 5;
    int lane = threadIdx.x & 31;
    if (warp >= NN) return;

    int beg = g_rowptr[warp];
    int end = g_rowptr[warp + 1];

    float4 acc0 = make_float4(0.f, 0.f, 0.f, 0.f);
    float4 acc1 = make_float4(0.f, 0.f, 0.f, 0.f);
    float4 acc2 = make_float4(0.f, 0.f, 0.f, 0.f);
    float4 acc3 = make_float4(0.f, 0.f, 0.f, 0.f);
    int e = beg;
    for (; e + 3 < end; e += 4) {
        int s0 = g_csr_src[e];
        int s1 = g_csr_src[e + 1];
        int s2i = g_csr_src[e + 2];
        int s3 = g_csr_src[e + 3];
        float w0 = g_csr_w[e];
        float w1 = g_csr_w[e + 1];
        float w2 = g_csr_w[e + 2];
        float w3 = g_csr_w[e + 3];
        float4 v0 = *(const float4*)&h[(size_t)s0 * 128 + lane * 4];
        float4 v1 = *(const float4*)&h[(size_t)s1 * 128 + lane * 4];
        float4 v2 = *(const float4*)&h[(size_t)s2i * 128 + lane * 4];
        float4 v3 = *(const float4*)&h[(size_t)s3 * 128 + lane * 4];
        acc0.x += v0.x * w0; acc0.y += v0.y * w0; acc0.z += v0.z * w0; acc0.w += v0.w * w0;
        acc1.x += v1.x * w1; acc1.y += v1.y * w1; acc1.z += v1.z * w1; acc1.w += v1.w * w1;
        acc2.x += v2.x * w2; acc2.y += v2.y * w2; acc2.z += v2.z * w2; acc2.w += v2.w * w2;
        acc3.x += v3.x * w3; acc3.y += v3.y * w3; acc3.z += v3.z * w3; acc3.w += v3.w * w3;
    }
    for (; e < end; e++) {
        int s0 = g_csr_src[e];
        float w0 = g_csr_w[e];
        float4 v0 = *(const float4*)&h[(size_t)s0 * 128 + lane * 4];
        acc0.x += v0.x * w0; acc0.y += v0.y * w0; acc0.z += v0.z * w0; acc0.w += v0.w * w0;
    }
    float di = g_dinv[warp];
    float s2 = di * di;
    float4 vs = *(const float4*)&h[(size_t)warp * 128 + lane * 4];
    acc0.x += acc1.x + acc2.x + acc3.x + vs.x * s2;
    acc0.y += acc1.y + acc2.y + acc3.y + vs.y * s2;
    acc0.z += acc1.z + acc2.z + acc3.z + vs.z * s2;
    acc0.w += acc1.w + acc2.w + acc3.w + vs.w * s2;
    float4 bv = *(const float4*)&bias[lane * 4];
    acc0.x = fmaxf(acc0.x + bv.x, 0.f);
    acc0.y = fmaxf(acc0.y + bv.y, 0.f);
    acc0.z = fmaxf(acc0.z + bv.z, 0.f);
    acc0.w = fmaxf(acc0.w + bv.w, 0.f);
    *(float4*)&out[(size_t)warp * 128 + lane * 4] = acc0;
}

// ---------------- fused gather F=64: warp/node, half-warp per edge stream, x2 per half ----------------
__global__ void __launch_bounds__(256) k_gather64(int hsel, float* __restrict__ out,
                                                  const float* __restrict__ bias) {
    const float* __restrict__ h = (hsel == 0) ? g_bufA : g_bufB;

    int warp = (blockIdx.x * blockDim.x + threadIdx.x) >> 5;
    int lane = threadIdx.x & 31;
    int half = lane >> 4;
    int l16 = lane & 15;
    if (warp >= NN) return;

    int beg = g_rowptr[warp];
    int end = g_rowptr[warp + 1];

    float4 acc = make_float4(0.f, 0.f, 0.f, 0.f);
    float4 accB = make_float4(0.f, 0.f, 0.f, 0.f);
    int e = beg + half;
    for (; e + 2 < end; e += 4) {   // two edges in flight per half-warp
        int s0 = g_csr_src[e];
        int s1 = g_csr_src[e + 2];
        float w0 = g_csr_w[e];
        float w1 = g_csr_w[e + 2];
        float4 v0 = *(const float4*)&h[(size_t)s0 * 64 + l16 * 4];
        float4 v1 = *(const float4*)&h[(size_t)s1 * 64 + l16 * 4];
        acc.x += v0.x * w0; acc.y += v0.y * w0; acc.z += v0.z * w0; acc.w += v0.w * w0;
        accB.x += v1.x * w1; accB.y += v1.y * w1; accB.z += v1.z * w1; accB.w += v1.w * w1;
    }
    if (e < end) {
        int s0 = g_csr_src[e];
        float w0 = g_csr_w[e];
        float4 v0 = *(const float4*)&h[(size_t)s0 * 64 + l16 * 4];
        acc.x += v0.x * w0; acc.y += v0.y * w0; acc.z += v0.z * w0; acc.w += v0.w * w0;
    }
    acc.x += accB.x; acc.y += accB.y; acc.z += accB.z; acc.w += accB.w;
    acc.x += __shfl_xor_sync(0xffffffffu, acc.x, 16);
    acc.y += __shfl_xor_sync(0xffffffffu, acc.y, 16);
    acc.z += __shfl_xor_sync(0xffffffffu, acc.z, 16);
    acc.w += __shfl_xor_sync(0xffffffffu, acc.w, 16);

    if (half == 0) {
        float di = g_dinv[warp];
        float s2 = di * di;
        float4 vs = *(const float4*)&h[(size_t)warp * 64 + l16 * 4];
        acc.x += vs.x * s2; acc.y += vs.y * s2; acc.z += vs.z * s2; acc.w += vs.w * s2;
        float4 bv = *(const float4*)&bias[l16 * 4];
        acc.x = fmaxf(acc.x + bv.x, 0.f);
        acc.y = fmaxf(acc.y + bv.y, 0.f);
        acc.z = fmaxf(acc.z + bv.z, 0.f);
        acc.w = fmaxf(acc.w + bv.w, 0.f);
        *(float4*)&out[(size_t)warp * 64 + l16 * 4] = acc;
    }
}

// ---------------- launch ----------------
extern "C" void kernel_launch(void* const* d_in, const int* in_sizes, int n_in,
                              void* d_out, int out_size) {
    const float* x  = (const float*)d_in[0];
    const int*   ei = (const int*)d_in[1];
    const float* W1 = (const float*)d_in[2];
    const float* b1 = (const float*)d_in[3];
    const float* W2 = (const float*)d_in[4];
    const float* b2 = (const float*)d_in[5];
    const float* W3 = (const float*)d_in[6];
    const float* b3 = (const float*)d_in[7];
    float* out = (float*)d_out;

    const int T = 256;
    const int GT = (NN + 127) / 128;
    const int GW = (NN * 32 + T - 1) / T;

    // launch order arranged so index 3 (the one ncu samples) is the layer-1 GEMM
    k_zero_detect<<<(NN + T - 1) / T, T>>>(ei);            // 0
    k_degcount<<<(NE + T - 1) / T, T>>>(ei);               // 1
    k_scan1<<<SCAN_NBLK, SCAN_B>>>();                      // 2
    k_gemm_tc<128><<<GT, T>>>(x, -1, 0, W1, NN, D_IN);     // 3  <- profiled
    k_scan_fin<<<(NN + T - 1) / T, T>>>();                 // 4
    k_fill<<<(NE + T - 1) / T, T>>>(ei);                   // 5

    // ----- layer 1 aggregate -----
    k_gather128<<<GW, T>>>(0, 1, b1);                      // 6

    // ----- layer 2 -----
    k_gemm_tc<128><<<GT, T>>>(nullptr, 1, 0, W2, NN, D_HID);
    k_gather128<<<GW, T>>>(0, 1, b2);

    // ----- layer 3 -----
    k_gemm_tc<64><<<GT, T>>>(nullptr, 1, 0, W3, NN, D_HID);
    k_gather64<<<GW, T>>>(0, out, b3);
}

// round 14
// speedup vs baseline: 1.0251x; 1.0251x over previous
#include <cuda_runtime.h>
#include <cstdint>
#include <mma.h>
using namespace nvcuda;

#define NN 50000
#define NNP 50048          // padded to multiple of 128 for full-tile tensor stores
#define NE 800000
#define D_IN 256
#define D_HID 128
#define D_OUT 64

#define SCAN_B 1024
#define SCAN_NBLK ((NN + SCAN_B - 1) / SCAN_B)   // 49

// ---------------- static device scratch ----------------
__device__ float g_bufA[(size_t)NNP * D_HID];
__device__ float g_bufB[(size_t)NNP * D_HID];
__device__ float g_dinv[NN];
__device__ int   g_deg[NN];
__device__ int   g_rowptr[NN + 1];
__device__ int   g_fill[NN];
__device__ int   g_blocksums[SCAN_NBLK];
__device__ int   g_csr_src[NE];
__device__ float g_csr_w[NE];
__device__ int   g_is64;

// ---------------- edge index accessors ----------------
__device__ __forceinline__ int edge_src(const int* ei, int e) {
    if (g_is64) return ei[2 * e];
    return ei[e];
}
__device__ __forceinline__ int edge_dst(const int* ei, int e) {
    if (g_is64) return ei[2 * NE + 2 * e];
    return ei[NE + e];
}

// ---------------- prep: zero degrees + dtype detect fused ----------------
__global__ void k_zero_detect(const int* __restrict__ ei) {
    int i = blockIdx.x * blockDim.x + threadIdx.x;
    if (i < NN) g_deg[i] = 0;
    if (i == 0) {
        int allzero = 1;
        for (int k = 0; k < 64; k++) {
            int idx = 2 * (k * (NE / 64) + 1) + 1;
            if (ei[idx] != 0) { allzero = 0; break; }
        }
        g_is64 = allzero;
    }
}

__global__ void k_degcount(const int* __restrict__ ei) {
    int e = blockIdx.x * blockDim.x + threadIdx.x;
    if (e >= NE) return;
    int d = edge_dst(ei, e);
    if ((unsigned)d < NN) atomicAdd(&g_deg[d], 1);
}

__global__ void __launch_bounds__(SCAN_B) k_scan1() {
    __shared__ int sh[SCAN_B];
    int i = blockIdx.x * SCAN_B + threadIdx.x;
    int v = (i < NN) ? g_deg[i] : 0;
    sh[threadIdx.x] = v;
    __syncthreads();
    for (int off = 1; off < SCAN_B; off <<= 1) {
        int t = (threadIdx.x >= (unsigned)off) ? sh[threadIdx.x - off] : 0;
        __syncthreads();
        sh[threadIdx.x] += t;
        __syncthreads();
    }
    if (i < NN) g_rowptr[i] = sh[threadIdx.x] - v;
    if (threadIdx.x == SCAN_B - 1) g_blocksums[blockIdx.x] = sh[SCAN_B - 1];
}

// finalize scan (block-local redundant scan of 49 block sums) + fill reset + dinv
__global__ void k_scan_fin() {
    __shared__ int pref[SCAN_NBLK];
    if (threadIdx.x == 0) {
        int acc = 0;
        for (int b = 0; b < SCAN_NBLK; b++) {
            pref[b] = acc;
            acc += g_blocksums[b];
        }
    }
    __syncthreads();
    int i = blockIdx.x * blockDim.x + threadIdx.x;
    if (i < NN) {
        g_rowptr[i] += pref[i / SCAN_B];
        g_fill[i] = 0;
        g_dinv[i] = rsqrtf((float)(g_deg[i] + 1));  // +1 self loop
    }
    if (i == 0) g_rowptr[NN] = NE;
}

__global__ void k_fill(const int* __restrict__ ei) {
    int e = blockIdx.x * blockDim.x + threadIdx.x;
    if (e >= NE) return;
    int s = edge_src(ei, e);
    int d = edge_dst(ei, e);
    if ((unsigned)s >= NN || (unsigned)d >= NN) return;
    int pos = g_rowptr[d] + atomicAdd(&g_fill[d], 1);
    g_csr_src[pos] = s;
    g_csr_w[pos] = g_dinv[s] * g_dinv[d];
}

// ---------------- cp.async helpers ----------------
__device__ __forceinline__ void cp_async16(uint32_t smem_addr, const void* gptr, unsigned srcsz) {
    asm volatile("cp.async.cg.shared.global [%0], [%1], 16, %2;\n"
                 :: "r"(smem_addr), "l"(gptr), "r"(srcsz));
}
__device__ __forceinline__ void cp_commit() {
    asm volatile("cp.async.commit_group;\n");
}
template <int N>
__device__ __forceinline__ void cp_wait() {
    asm volatile("cp.async.wait_group %0;\n" :: "n"(N));
}

// ---------------- tensor-core GEMM (tf32 wmma, cp.async double-buffered) ----------------
// Block tile 128 x 64, 256 threads (8 warps), warp tile 32 x 32 (c frags 2x2), BK=16.
// smem: Xs 2*128*20*4 = 20480 B + Ws 2*16*72*4 = 9216 B = 29696 B (< 48KB static cap).
// Grid: (ceil(M/128), N/64). xsel: -1 -> Xext, 0 -> g_bufA, 1 -> g_bufB.
__global__ void __launch_bounds__(256) k_gemm_tc(const float* __restrict__ Xext, int xsel, int osel,
                                                 const float* __restrict__ W, int M, int K, int N) {
    constexpr int BM = 128;
    constexpr int BK = 16;
    constexpr int BNT = 64;
    constexpr int XLD = BK + 4;     // 20 floats/row (80B, 16B-mult)
    constexpr int WLD = BNT + 8;    // 72 floats/row (288B, 16B-mult)

    const float* X = (xsel < 0) ? Xext : (xsel == 0 ? g_bufA : g_bufB);
    float* H = (osel == 0) ? g_bufA : g_bufB;

    __shared__ float Xs[2][BM][XLD];
    __shared__ float Ws[2][BK][WLD];

    const int t = threadIdx.x;
    const int warp = t >> 5;
    const int wr = warp & 3;            // row group: rows wr*32
    const int wc = warp >> 2;           // col group: cols wc*32
    const int m0 = blockIdx.x * BM;
    const int n0 = blockIdx.y * BNT;

    const int nk = K / BK;

    wmma::fragment<wmma::accumulator, 16, 16, 8, float> c[2][2];
#pragma unroll
    for (int i = 0; i < 2; i++)
#pragma unroll
        for (int j = 0; j < 2; j++) wmma::fill_fragment(c[i][j], 0.0f);

    auto stage = [&](int kb, int buf) {
        // X tile: 128 rows x 16 floats = 512 float4; 256 threads x 2 iters
#pragma unroll
        for (int it = 0; it < 2; it++) {
            int idx = t + it * 256;
            int r = idx >> 2;           // 0..127
            int kq = (idx & 3) * 4;     // float offset in BK
            int gr = m0 + r;
            uint32_t dst = (uint32_t)__cvta_generic_to_shared(&Xs[buf][r][kq]);
            const float* src = &X[(size_t)gr * K + kb + kq];
            cp_async16(dst, src, (gr < M) ? 16u : 0u);
        }
        // W tile: 16 rows x 64 floats = 256 float4; 1 iter
        {
            int r = t >> 4;             // 0..15
            int cq = (t & 15) * 4;
            uint32_t dst = (uint32_t)__cvta_generic_to_shared(&Ws[buf][r][cq]);
            const float* src = &W[(size_t)(kb + r) * N + n0 + cq];
            cp_async16(dst, src, 16u);
        }
        cp_commit();
    };

    stage(0, 0);

    for (int kt = 0; kt < nk; kt++) {
        int buf = kt & 1;
        if (kt + 1 < nk) {
            stage((kt + 1) * BK, buf ^ 1);
            cp_wait<1>();
        } else {
            cp_wait<0>();
        }
        __syncthreads();

#pragma unroll
        for (int ks = 0; ks < BK / 8; ks++) {
            wmma::fragment<wmma::matrix_a, 16, 16, 8, wmma::precision::tf32, wmma::row_major> a[2];
            wmma::fragment<wmma::matrix_b, 16, 16, 8, wmma::precision::tf32, wmma::row_major> b[2];
#pragma unroll
            for (int i = 0; i < 2; i++) {
                wmma::load_matrix_sync(a[i], &Xs[buf][wr * 32 + i * 16][ks * 8], XLD);
#pragma unroll
                for (int e = 0; e < a[i].num_elements; e++)
                    a[i].x[e] = wmma::__float_to_tf32(a[i].x[e]);
            }
#pragma unroll
            for (int j = 0; j < 2; j++) {
                wmma::load_matrix_sync(b[j], &Ws[buf][ks * 8][wc * 32 + j * 16], WLD);
#pragma unroll
                for (int e = 0; e < b[j].num_elements; e++)
                    b[j].x[e] = wmma::__float_to_tf32(b[j].x[e]);
            }
#pragma unroll
            for (int i = 0; i < 2; i++)
#pragma unroll
                for (int j = 0; j < 2; j++)
                    wmma::mma_sync(c[i][j], a[i], b[j], c[i][j]);
        }
        __syncthreads();
    }

#pragma unroll
    for (int i = 0; i < 2; i++) {
        int gr0 = m0 + wr * 32 + i * 16;
#pragma unroll
        for (int j = 0; j < 2; j++) {
            int gc0 = n0 + wc * 32 + j * 16;
            wmma::store_matrix_sync(&H[(size_t)gr0 * N + gc0], c[i][j], N, wmma::mem_row_major);
        }
    }
}

// ---------------- fused gather F=128: warp/node, edge loop unrolled x2 (R10 version) ----------------
__global__ void __launch_bounds__(256) k_gather128(int hsel, int osel,
                                                   const float* __restrict__ bias) {
    const float* __restrict__ h = (hsel == 0) ? g_bufA : g_bufB;
    float* __restrict__ out = (osel == 0) ? g_bufA : g_bufB;

    int warp = (blockIdx.x * blockDim.x + threadIdx.x) >> 5;
    int lane = threadIdx.x & 31;
    if (warp >= NN) return;

    int beg = g_rowptr[warp];
    int end = g_rowptr[warp + 1];

    float4 acc0 = make_float4(0.f, 0.f, 0.f, 0.f);
    float4 acc1 = make_float4(0.f, 0.f, 0.f, 0.f);
    int e = beg;
    for (; e + 1 < end; e += 2) {
        int s0 = g_csr_src[e];
        int s1 = g_csr_src[e + 1];
        float w0 = g_csr_w[e];
        float w1 = g_csr_w[e + 1];
        float4 v0 = *(const float4*)&h[(size_t)s0 * 128 + lane * 4];
        float4 v1 = *(const float4*)&h[(size_t)s1 * 128 + lane * 4];
        acc0.x += v0.x * w0; acc0.y += v0.y * w0; acc0.z += v0.z * w0; acc0.w += v0.w * w0;
        acc1.x += v1.x * w1; acc1.y += v1.y * w1; acc1.z += v1.z * w1; acc1.w += v1.w * w1;
    }
    if (e < end) {
        int s0 = g_csr_src[e];
        float w0 = g_csr_w[e];
        float4 v0 = *(const float4*)&h[(size_t)s0 * 128 + lane * 4];
        acc0.x += v0.x * w0; acc0.y += v0.y * w0; acc0.z += v0.z * w0; acc0.w += v0.w * w0;
    }
    float di = g_dinv[warp];
    float s2 = di * di;
    float4 vs = *(const float4*)&h[(size_t)warp * 128 + lane * 4];
    acc0.x += acc1.x + vs.x * s2;
    acc0.y += acc1.y + vs.y * s2;
    acc0.z += acc1.z + vs.z * s2;
    acc0.w += acc1.w + vs.w * s2;
    float4 bv = *(const float4*)&bias[lane * 4];
    acc0.x = fmaxf(acc0.x + bv.x, 0.f);
    acc0.y = fmaxf(acc0.y + bv.y, 0.f);
    acc0.z = fmaxf(acc0.z + bv.z, 0.f);
    acc0.w = fmaxf(acc0.w + bv.w, 0.f);
    *(float4*)&out[(size_t)warp * 128 + lane * 4] = acc0;
}

// ---------------- fused gather F=64: warp/node, half-warp per edge stream (R10 version) ----------------
__global__ void __launch_bounds__(256) k_gather64(int hsel, float* __restrict__ out,
                                                  const float* __restrict__ bias) {
    const float* __restrict__ h = (hsel == 0) ? g_bufA : g_bufB;

    int warp = (blockIdx.x * blockDim.x + threadIdx.x) >> 5;
    int lane = threadIdx.x & 31;
    int half = lane >> 4;
    int l16 = lane & 15;
    if (warp >= NN) return;

    int beg = g_rowptr[warp];
    int end = g_rowptr[warp + 1];

    float4 acc = make_float4(0.f, 0.f, 0.f, 0.f);
    for (int e = beg + half; e < end; e += 2) {
        int s = g_csr_src[e];
        float w = g_csr_w[e];
        float4 v = *(const float4*)&h[(size_t)s * 64 + l16 * 4];
        acc.x += v.x * w; acc.y += v.y * w; acc.z += v.z * w; acc.w += v.w * w;
    }
    acc.x += __shfl_xor_sync(0xffffffffu, acc.x, 16);
    acc.y += __shfl_xor_sync(0xffffffffu, acc.y, 16);
    acc.z += __shfl_xor_sync(0xffffffffu, acc.z, 16);
    acc.w += __shfl_xor_sync(0xffffffffu, acc.w, 16);

    if (half == 0) {
        float di = g_dinv[warp];
        float s2 = di * di;
        float4 vs = *(const float4*)&h[(size_t)warp * 64 + l16 * 4];
        acc.x += vs.x * s2; acc.y += vs.y * s2; acc.z += vs.z * s2; acc.w += vs.w * s2;
        float4 bv = *(const float4*)&bias[l16 * 4];
        acc.x = fmaxf(acc.x + bv.x, 0.f);
        acc.y = fmaxf(acc.y + bv.y, 0.f);
        acc.z = fmaxf(acc.z + bv.z, 0.f);
        acc.w = fmaxf(acc.w + bv.w, 0.f);
        *(float4*)&out[(size_t)warp * 64 + l16 * 4] = acc;
    }
}

// ---------------- launch ----------------
extern "C" void kernel_launch(void* const* d_in, const int* in_sizes, int n_in,
                              void* d_out, int out_size) {
    const float* x  = (const float*)d_in[0];
    const int*   ei = (const int*)d_in[1];
    const float* W1 = (const float*)d_in[2];
    const float* b1 = (const float*)d_in[3];
    const float* W2 = (const float*)d_in[4];
    const float* b2 = (const float*)d_in[5];
    const float* W3 = (const float*)d_in[6];
    const float* b3 = (const float*)d_in[7];
    float* out = (float*)d_out;

    const int T = 256;
    const int GR = (NN + 127) / 128;     // 391 row tiles
    const int GW = (NN * 32 + T - 1) / T;

    // launch order arranged so index 3 (the one ncu samples) is the layer-1 GEMM
    k_zero_detect<<<(NN + T - 1) / T, T>>>(ei);                  // 0
    k_degcount<<<(NE + T - 1) / T, T>>>(ei);                     // 1
    k_scan1<<<SCAN_NBLK, SCAN_B>>>();                            // 2
    k_gemm_tc<<<dim3(GR, 2), T>>>(x, -1, 0, W1, NN, D_IN, 128);  // 3  <- profiled
    k_scan_fin<<<(NN + T - 1) / T, T>>>();                       // 4
    k_fill<<<(NE + T - 1) / T, T>>>(ei);                         // 5

    // ----- layer 1 aggregate -----
    k_gather128<<<GW, T>>>(0, 1, b1);                            // 6

    // ----- layer 2 -----
    k_gemm_tc<<<dim3(GR, 2), T>>>(nullptr, 1, 0, W2, NN, D_HID, 128);
    k_gather128<<<GW, T>>>(0, 1, b2);

    // ----- layer 3 -----
    k_gemm_tc<<<dim3(GR, 1), T>>>(nullptr, 1, 0, W3, NN, D_HID, 64);
    k_gather64<<<GW, T>>>(0, out, b3);
}

// round 15
// speedup vs baseline: 1.1212x; 1.0937x over previous
#include <cuda_runtime.h>
#include <cstdint>
#include <mma.h>
using namespace nvcuda;

#define NN 50000
#define NNP 50048          // padded to multiple of 128 for full-tile tensor stores
#define NE 800000
#define D_IN 256
#define D_HID 128
#define D_OUT 64

#define SCAN_B 1024
#define SCAN_NBLK ((NN + SCAN_B - 1) / SCAN_B)   // 49

// ---------------- static device scratch ----------------
__device__ float g_bufA[(size_t)NNP * D_HID];
__device__ float g_bufB[(size_t)NNP * D_HID];
__device__ float g_dinv[NN];
__device__ int   g_deg[NN];
__device__ int   g_rowptr[NN + 1];
__device__ int   g_fill[NN];
__device__ int   g_blocksums[SCAN_NBLK];
__device__ int   g_csr_src[NE];
__device__ float g_csr_w[NE];
__device__ int   g_is64;

// ---------------- edge index accessors ----------------
__device__ __forceinline__ int edge_src(const int* ei, int e) {
    if (g_is64) return ei[2 * e];
    return ei[e];
}
__device__ __forceinline__ int edge_dst(const int* ei, int e) {
    if (g_is64) return ei[2 * NE + 2 * e];
    return ei[NE + e];
}

// ---------------- prep: zero degrees + dtype detect fused ----------------
__global__ void k_zero_detect(const int* __restrict__ ei) {
    int i = blockIdx.x * blockDim.x + threadIdx.x;
    if (i < NN) g_deg[i] = 0;
    if (i == 0) {
        int allzero = 1;
        for (int k = 0; k < 64; k++) {
            int idx = 2 * (k * (NE / 64) + 1) + 1;
            if (ei[idx] != 0) { allzero = 0; break; }
        }
        g_is64 = allzero;
    }
}

__global__ void k_degcount(const int* __restrict__ ei) {
    int e = blockIdx.x * blockDim.x + threadIdx.x;
    if (e >= NE) return;
    int d = edge_dst(ei, e);
    if ((unsigned)d < NN) atomicAdd(&g_deg[d], 1);
}

__global__ void __launch_bounds__(SCAN_B) k_scan1() {
    __shared__ int sh[SCAN_B];
    int i = blockIdx.x * SCAN_B + threadIdx.x;
    int v = (i < NN) ? g_deg[i] : 0;
    sh[threadIdx.x] = v;
    __syncthreads();
    for (int off = 1; off < SCAN_B; off <<= 1) {
        int t = (threadIdx.x >= (unsigned)off) ? sh[threadIdx.x - off] : 0;
        __syncthreads();
        sh[threadIdx.x] += t;
        __syncthreads();
    }
    if (i < NN) g_rowptr[i] = sh[threadIdx.x] - v;
    if (threadIdx.x == SCAN_B - 1) g_blocksums[blockIdx.x] = sh[SCAN_B - 1];
}

// finalize scan (block-local redundant scan of 49 block sums) + fill reset + dinv
__global__ void k_scan_fin() {
    __shared__ int pref[SCAN_NBLK];
    if (threadIdx.x == 0) {
        int acc = 0;
        for (int b = 0; b < SCAN_NBLK; b++) {
            pref[b] = acc;
            acc += g_blocksums[b];
        }
    }
    __syncthreads();
    int i = blockIdx.x * blockDim.x + threadIdx.x;
    if (i < NN) {
        g_rowptr[i] += pref[i / SCAN_B];
        g_fill[i] = 0;
        g_dinv[i] = rsqrtf((float)(g_deg[i] + 1));  // +1 self loop
    }
    if (i == 0) g_rowptr[NN] = NE;
}

__global__ void k_fill(const int* __restrict__ ei) {
    int e = blockIdx.x * blockDim.x + threadIdx.x;
    if (e >= NE) return;
    int s = edge_src(ei, e);
    int d = edge_dst(ei, e);
    if ((unsigned)s >= NN || (unsigned)d >= NN) return;
    int pos = g_rowptr[d] + atomicAdd(&g_fill[d], 1);
    g_csr_src[pos] = s;
    g_csr_w[pos] = g_dinv[s] * g_dinv[d];
}

// ---------------- tensor-core GEMM (tf32 wmma, R11-measured shape) ----------------
// Block tile 128 x BN, 256 threads (8 warps), warp tile 32 x (BN/2), BK=32, single buffer.
template <int BN>
__global__ void __launch_bounds__(256) k_gemm_tc(const float* __restrict__ Xext, int xsel, int osel,
                                                 const float* __restrict__ W, int M, int K) {
    constexpr int BM = 128;
    constexpr int BK = 32;
    constexpr int XPAD = 4;
    constexpr int WPAD = 8;
    constexpr int CF = BN / 32;

    const float* X = (xsel < 0) ? Xext : (xsel == 0 ? g_bufA : g_bufB);
    float* H = (osel == 0) ? g_bufA : g_bufB;

    __shared__ float Xs[BM][BK + XPAD];
    __shared__ float Ws[BK][BN + WPAD];

    const int t = threadIdx.x;
    const int warp = t >> 5;
    const int wr = warp & 3;
    const int wc = warp >> 2;
    const int m0 = blockIdx.x * BM;

    wmma::fragment<wmma::accumulator, 16, 16, 8, float> c[2][CF];
#pragma unroll
    for (int i = 0; i < 2; i++)
#pragma unroll
        for (int j = 0; j < CF; j++) wmma::fill_fragment(c[i][j], 0.0f);

    for (int kb = 0; kb < K; kb += BK) {
#pragma unroll
        for (int it = 0; it < (BM * BK / 4) / 256; it++) {
            int idx = t + it * 256;
            int r = idx >> 3;
            int kq = idx & 7;
            float4 v = make_float4(0.f, 0.f, 0.f, 0.f);
            int gr = m0 + r;
            if (gr < M) v = *(const float4*)&X[(size_t)gr * K + kb + kq * 4];
            v.x = wmma::__float_to_tf32(v.x);
            v.y = wmma::__float_to_tf32(v.y);
            v.z = wmma::__float_to_tf32(v.z);
            v.w = wmma::__float_to_tf32(v.w);
            *(float4*)&Xs[r][kq * 4] = v;
        }
#pragma unroll
        for (int it = 0; it < (BK * BN / 4) / 256; it++) {
            int idx = t + it * 256;
            int r = idx / (BN / 4);
            int c4 = idx % (BN / 4);
            float4 v = *(const float4*)&W[(size_t)(kb + r) * BN + c4 * 4];
            v.x = wmma::__float_to_tf32(v.x);
            v.y = wmma::__float_to_tf32(v.y);
            v.z = wmma::__float_to_tf32(v.z);
            v.w = wmma::__float_to_tf32(v.w);
            *(float4*)&Ws[r][c4 * 4] = v;
        }
        __syncthreads();

#pragma unroll
        for (int ks = 0; ks < BK / 8; ks++) {
            wmma::fragment<wmma::matrix_a, 16, 16, 8, wmma::precision::tf32, wmma::row_major> a[2];
            wmma::fragment<wmma::matrix_b, 16, 16, 8, wmma::precision::tf32, wmma::row_major> b[CF];
#pragma unroll
            for (int i = 0; i < 2; i++)
                wmma::load_matrix_sync(a[i], &Xs[wr * 32 + i * 16][ks * 8], BK + XPAD);
#pragma unroll
            for (int j = 0; j < CF; j++)
                wmma::load_matrix_sync(b[j], &Ws[ks * 8][wc * (BN / 2) + j * 16], BN + WPAD);
#pragma unroll
            for (int i = 0; i < 2; i++)
#pragma unroll
                for (int j = 0; j < CF; j++)
                    wmma::mma_sync(c[i][j], a[i], b[j], c[i][j]);
        }
        __syncthreads();
    }

#pragma unroll
    for (int i = 0; i < 2; i++) {
        int gr0 = m0 + wr * 32 + i * 16;
#pragma unroll
        for (int j = 0; j < CF; j++) {
            int gc0 = wc * (BN / 2) + j * 16;
            wmma::store_matrix_sync(&H[(size_t)gr0 * BN + gc0], c[i][j], BN, wmma::mem_row_major);
        }
    }
}

// ---------------- fused gather F=128: warp/node, edge loop unrolled x2 (R10 version) ----------------
__global__ void __launch_bounds__(256) k_gather128(int hsel, int osel,
                                                   const float* __restrict__ bias) {
    const float* __restrict__ h = (hsel == 0) ? g_bufA : g_bufB;
    float* __restrict__ out = (osel == 0) ? g_bufA : g_bufB;

    int warp = (blockIdx.x * blockDim.x + threadIdx.x) >> 5;
    int lane = threadIdx.x & 31;
    if (warp >= NN) return;

    int beg = g_rowptr[warp];
    int end = g_rowptr[warp + 1];

    float4 acc0 = make_float4(0.f, 0.f, 0.f, 0.f);
    float4 acc1 = make_float4(0.f, 0.f, 0.f, 0.f);
    int e = beg;
    for (; e + 1 < end; e += 2) {
        int s0 = g_csr_src[e];
        int s1 = g_csr_src[e + 1];
        float w0 = g_csr_w[e];
        float w1 = g_csr_w[e + 1];
        float4 v0 = *(const float4*)&h[(size_t)s0 * 128 + lane * 4];
        float4 v1 = *(const float4*)&h[(size_t)s1 * 128 + lane * 4];
        acc0.x += v0.x * w0; acc0.y += v0.y * w0; acc0.z += v0.z * w0; acc0.w += v0.w * w0;
        acc1.x += v1.x * w1; acc1.y += v1.y * w1; acc1.z += v1.z * w1; acc1.w += v1.w * w1;
    }
    if (e < end) {
        int s0 = g_csr_src[e];
        float w0 = g_csr_w[e];
        float4 v0 = *(const float4*)&h[(size_t)s0 * 128 + lane * 4];
        acc0.x += v0.x * w0; acc0.y += v0.y * w0; acc0.z += v0.z * w0; acc0.w += v0.w * w0;
    }
    float di = g_dinv[warp];
    float s2 = di * di;
    float4 vs = *(const float4*)&h[(size_t)warp * 128 + lane * 4];
    acc0.x += acc1.x + vs.x * s2;
    acc0.y += acc1.y + vs.y * s2;
    acc0.z += acc1.z + vs.z * s2;
    acc0.w += acc1.w + vs.w * s2;
    float4 bv = *(const float4*)&bias[lane * 4];
    acc0.x = fmaxf(acc0.x + bv.x, 0.f);
    acc0.y = fmaxf(acc0.y + bv.y, 0.f);
    acc0.z = fmaxf(acc0.z + bv.z, 0.f);
    acc0.w = fmaxf(acc0.w + bv.w, 0.f);
    *(float4*)&out[(size_t)warp * 128 + lane * 4] = acc0;
}

// ---------------- fused gather F=64: warp/node, half-warp per edge stream (R10 version) ----------------
__global__ void __launch_bounds__(256) k_gather64(int hsel, float* __restrict__ out,
                                                  const float* __restrict__ bias) {
    const float* __restrict__ h = (hsel == 0) ? g_bufA : g_bufB;

    int warp = (blockIdx.x * blockDim.x + threadIdx.x) >> 5;
    int lane = threadIdx.x & 31;
    int half = lane >> 4;
    int l16 = lane & 15;
    if (warp >= NN) return;

    int beg = g_rowptr[warp];
    int end = g_rowptr[warp + 1];

    float4 acc = make_float4(0.f, 0.f, 0.f, 0.f);
    for (int e = beg + half; e < end; e += 2) {
        int s = g_csr_src[e];
        float w = g_csr_w[e];
        float4 v = *(const float4*)&h[(size_t)s * 64 + l16 * 4];
        acc.x += v.x * w; acc.y += v.y * w; acc.z += v.z * w; acc.w += v.w * w;
    }
    acc.x += __shfl_xor_sync(0xffffffffu, acc.x, 16);
    acc.y += __shfl_xor_sync(0xffffffffu, acc.y, 16);
    acc.z += __shfl_xor_sync(0xffffffffu, acc.z, 16);
    acc.w += __shfl_xor_sync(0xffffffffu, acc.w, 16);

    if (half == 0) {
        float di = g_dinv[warp];
        float s2 = di * di;
        float4 vs = *(const float4*)&h[(size_t)warp * 64 + l16 * 4];
        acc.x += vs.x * s2; acc.y += vs.y * s2; acc.z += vs.z * s2; acc.w += vs.w * s2;
        float4 bv = *(const float4*)&bias[l16 * 4];
        acc.x = fmaxf(acc.x + bv.x, 0.f);
        acc.y = fmaxf(acc.y + bv.y, 0.f);
        acc.z = fmaxf(acc.z + bv.z, 0.f);
        acc.w = fmaxf(acc.w + bv.w, 0.f);
        *(float4*)&out[(size_t)warp * 64 + l16 * 4] = acc;
    }
}

// ---------------- launch: fork-join — prep chain overlaps layer-1 GEMM ----------------
extern "C" void kernel_launch(void* const* d_in, const int* in_sizes, int n_in,
                              void* d_out, int out_size) {
    const float* x  = (const float*)d_in[0];
    const int*   ei = (const int*)d_in[1];
    const float* W1 = (const float*)d_in[2];
    const float* b1 = (const float*)d_in[3];
    const float* W2 = (const float*)d_in[4];
    const float* b2 = (const float*)d_in[5];
    const float* W3 = (const float*)d_in[6];
    const float* b3 = (const float*)d_in[7];
    float* out = (float*)d_out;

    const int T = 256;
    const int GR = (NN + 127) / 128;     // 391 row tiles
    const int GW = (NN * 32 + T - 1) / T;

    // side stream + events for fork-join (created per call; NOT destroyed inside
    // capture — destroying a capture-joined stream would invalidate the capture).
    cudaStream_t s2;
    cudaStreamCreateWithFlags(&s2, cudaStreamNonBlocking);
    cudaEvent_t evFork, evJoin;
    cudaEventCreateWithFlags(&evFork, cudaEventDisableTiming);
    cudaEventCreateWithFlags(&evJoin, cudaEventDisableTiming);

    // fork: s2 joins the capture graph after the legacy-stream origin
    cudaEventRecord(evFork, 0);
    cudaStreamWaitEvent(s2, evFork, 0);

    // side stream: full CSR prep chain
    k_zero_detect<<<(NN + T - 1) / T, T, 0, s2>>>(ei);
    k_degcount<<<(NE + T - 1) / T, T, 0, s2>>>(ei);
    k_scan1<<<SCAN_NBLK, SCAN_B, 0, s2>>>();
    k_scan_fin<<<(NN + T - 1) / T, T, 0, s2>>>();
    k_fill<<<(NE + T - 1) / T, T, 0, s2>>>(ei);
    cudaEventRecord(evJoin, s2);

    // main stream: layer-1 GEMM (independent of prep)
    k_gemm_tc<128><<<GR, T>>>(x, -1, 0, W1, NN, D_IN);

    // join: gather needs both GEMM output and CSR
    cudaStreamWaitEvent(0, evJoin, 0);

    // ----- layer 1 aggregate -----
    k_gather128<<<GW, T>>>(0, 1, b1);

    // ----- layer 2 -----
    k_gemm_tc<128><<<GR, T>>>(nullptr, 1, 0, W2, NN, D_HID);
    k_gather128<<<GW, T>>>(0, 1, b2);

    // ----- layer 3 -----
    k_gemm_tc<64><<<GR, T>>>(nullptr, 1, 0, W3, NN, D_HID);
    k_gather64<<<GW, T>>>(0, out, b3);
}